// round 5
// baseline (speedup 1.0000x reference)
#include <cuda_runtime.h>
#include <cstdint>

#define NB 2
#define NS 4096
#define NH 8
#define NDH 64
#define ND 512
#define NBH (NB*NH)

// Scratch (allocation-free rule: __device__ globals).
// g_Q/g_K/g_V hold tf32 *bits* (converted once in the projection epilogue).
__device__ uint32_t g_Q[(size_t)NBH * NS * NDH];
__device__ uint32_t g_K[(size_t)NBH * NS * NDH];
__device__ uint32_t g_V[(size_t)NBH * NS * NDH];
__device__ float    g_attn[(size_t)NB * NS * ND];

__device__ __forceinline__ uint32_t f2tf32(float v) {
    uint32_t u;
    asm("cvt.rna.tf32.f32 %0, %1;" : "=r"(u) : "f"(v));
    return u;
}

// D = A(16x8) * B(8x8) + D, tf32 inputs, f32 accum
__device__ __forceinline__ void mma_tf32(float* c, const uint32_t* a, const uint32_t* b) {
    asm volatile(
        "mma.sync.aligned.m16n8k8.row.col.f32.tf32.tf32.f32 "
        "{%0,%1,%2,%3}, {%4,%5,%6,%7}, {%8,%9}, {%0,%1,%2,%3};\n"
        : "+f"(c[0]), "+f"(c[1]), "+f"(c[2]), "+f"(c[3])
        : "r"(a[0]), "r"(a[1]), "r"(a[2]), "r"(a[3]), "r"(b[0]), "r"(b[1]));
}

__device__ __forceinline__ void cp_async16(uint32_t saddr, const void* gptr) {
    asm volatile("cp.async.cg.shared.global [%0], [%1], 16;\n"
                 :: "r"(saddr), "l"(gptr));
}
__device__ __forceinline__ void cp_commit() {
    asm volatile("cp.async.commit_group;\n");
}
template <int N>
__device__ __forceinline__ void cp_wait() {
    asm volatile("cp.async.wait_group %0;\n" :: "n"(N));
}

// ---------------------------------------------------------------------------
// GEMM: out[m,n] = sum_k A[m,k] * W[n,k]   (torch Linear, W row-major [N,K])
// CTA tile 64x64, 4 warps (each 16 rows x 64 cols), BK=32.
// smem tiles hold tf32 BITS (converted at fill) -> inner loop is LDS+MMA only.
// MODE 0: A = x, blockIdx.z selects {Wq,Wk,Wv}; writes head-split tf32 bits
//         into g_Q/g_K/g_V; Q scaled by 0.125 (= Dh^-0.5, exact pow2).
// MODE 1: A = g_attn; W = Wo; writes fp32 row-major [M,512] + bias into out.
// ---------------------------------------------------------------------------
template <int MODE>
__global__ __launch_bounds__(128) void gemm_kernel(
    const float* __restrict__ A,
    const float* __restrict__ W0, const float* __restrict__ W1,
    const float* __restrict__ W2,
    const float* __restrict__ bias, float* __restrict__ out)
{
    __shared__ uint32_t As[64][36];  // stride 36: conflict-free fragment access
    __shared__ uint32_t Bs[64][36];

    const int tid = threadIdx.x;
    const int warp = tid >> 5, lane = tid & 31, g = lane >> 2, t = lane & 3;
    const int m0 = blockIdx.x * 64, n0 = blockIdx.y * 64;

    const float* Ap = (MODE == 0) ? A : g_attn;
    const float* W = (MODE == 1) ? W0
                     : (blockIdx.z == 0 ? W0 : (blockIdx.z == 1 ? W1 : W2));

    float acc[8][4];
#pragma unroll
    for (int n = 0; n < 8; n++)
#pragma unroll
        for (int i = 0; i < 4; i++) acc[n][i] = 0.f;

    for (int kt = 0; kt < ND / 32; kt++) {
#pragma unroll
        for (int i = 0; i < 4; i++) {
            int idx = tid + i * 128;            // 512 float4 per tile
            int r = idx >> 3, c4 = (idx & 7) << 2;
            float4 a4 = *(const float4*)(Ap + (size_t)(m0 + r) * ND + kt * 32 + c4);
            float4 b4 = *(const float4*)(W + (size_t)(n0 + r) * ND + kt * 32 + c4);
            uint4 au, bu;
            au.x = f2tf32(a4.x); au.y = f2tf32(a4.y);
            au.z = f2tf32(a4.z); au.w = f2tf32(a4.w);
            bu.x = f2tf32(b4.x); bu.y = f2tf32(b4.y);
            bu.z = f2tf32(b4.z); bu.w = f2tf32(b4.w);
            *(uint4*)(&As[r][c4]) = au;
            *(uint4*)(&Bs[r][c4]) = bu;
        }
        __syncthreads();
#pragma unroll
        for (int ks = 0; ks < 4; ks++) {
            const int row = warp * 16 + g, col = ks * 8 + t;
            uint32_t a[4];
            a[0] = As[row][col];
            a[1] = As[row + 8][col];
            a[2] = As[row][col + 4];
            a[3] = As[row + 8][col + 4];
#pragma unroll
            for (int n = 0; n < 8; n++) {
                uint32_t b[2];
                b[0] = Bs[n * 8 + g][col];
                b[1] = Bs[n * 8 + g][col + 4];
                mma_tf32(acc[n], a, b);
            }
        }
        __syncthreads();
    }

    const int r = m0 + warp * 16 + g;
    if (MODE == 0) {
        uint32_t* dst = blockIdx.z == 0 ? g_Q : (blockIdx.z == 1 ? g_K : g_V);
        const float scl = (blockIdx.z == 0) ? 0.125f : 1.0f;
        const int bb = r >> 12, ss = r & (NS - 1);
#pragma unroll
        for (int n = 0; n < 8; n++) {
            const int c = n0 + n * 8 + 2 * t;
            const int hh = c >> 6, dd = c & 63;
            const size_t base = (((size_t)(bb * NH + hh)) * NS + ss) * NDH + dd;
            dst[base] = f2tf32(acc[n][0] * scl);
            dst[base + 1] = f2tf32(acc[n][1] * scl);
            dst[base + 8 * NDH] = f2tf32(acc[n][2] * scl);
            dst[base + 8 * NDH + 1] = f2tf32(acc[n][3] * scl);
        }
    } else {
#pragma unroll
        for (int n = 0; n < 8; n++) {
            const int c = n0 + n * 8 + 2 * t;
            const float b0v = bias[c], b1v = bias[c + 1];
            out[(size_t)r * ND + c] = acc[n][0] + b0v;
            out[(size_t)r * ND + c + 1] = acc[n][1] + b1v;
            out[(size_t)(r + 8) * ND + c] = acc[n][2] + b0v;
            out[(size_t)(r + 8) * ND + c + 1] = acc[n][3] + b1v;
        }
    }
}

// ---------------------------------------------------------------------------
// Flash attention: grid (S/64, B*H), 128 threads (4 warps, 16 Q-rows each).
// Q fragments preloaded into registers (tf32 bits). K/V streamed as tf32 bits
// through cp.async double-buffered smem. P staged in smem as tf32 bits.
// Inner loops: LDS + HMMA only (zero cvt).
// ---------------------------------------------------------------------------
#define KST 68   // K/P stride: conflict-free for (4g+t) fragment patterns
#define VST 72   // V stride: conflict-free for (8t+g) fragment patterns
#define KV_TILE (64 * KST)
#define VV_TILE (64 * VST)
#define FLASH_SMEM ((2 * KV_TILE + 2 * VV_TILE + 64 * KST) * sizeof(uint32_t))

__global__ __launch_bounds__(128) void flash_kernel() {
    extern __shared__ uint32_t sm[];
    uint32_t* KsB = sm;                       // 2 stages
    uint32_t* VsB = sm + 2 * KV_TILE;         // 2 stages
    uint32_t* Ps  = sm + 2 * KV_TILE + 2 * VV_TILE;

    const int tid = threadIdx.x;
    const int warp = tid >> 5, lane = tid & 31, g = lane >> 2, t = lane & 3;
    const int bh = blockIdx.y, qt = blockIdx.x;
    const int row = warp * 16 + g;

    const uint32_t* Qg = g_Q + (size_t)(bh * NS + qt * 64) * NDH;
    const uint32_t* Kg = g_K + (size_t)bh * NS * NDH;
    const uint32_t* Vg = g_V + (size_t)bh * NS * NDH;

    // Preload Q fragments (resident whole kernel): 32 regs of tf32 bits
    uint32_t qf[8][4];
#pragma unroll
    for (int ks = 0; ks < 8; ks++) {
        const int col = ks * 8 + t;
        qf[ks][0] = Qg[row * NDH + col];
        qf[ks][1] = Qg[(row + 8) * NDH + col];
        qf[ks][2] = Qg[row * NDH + col + 4];
        qf[ks][3] = Qg[(row + 8) * NDH + col + 4];
    }

    float o[8][4];
#pragma unroll
    for (int n = 0; n < 8; n++)
#pragma unroll
        for (int i = 0; i < 4; i++) o[n][i] = 0.f;
    float m0 = -1e30f, m1 = -1e30f, l0 = 0.f, l1 = 0.f;

    const int r16 = tid >> 4, c16 = (tid & 15) << 2;   // each thread: 8 rows apart x8
    // prologue: stage 0
    {
        const uint32_t* kp = Kg;
        const uint32_t* vp = Vg;
#pragma unroll
        for (int i = 0; i < 8; i++) {
            int r = r16 + i * 8;
            cp_async16((uint32_t)__cvta_generic_to_shared(KsB + r * KST + c16),
                       kp + r * NDH + c16);
            cp_async16((uint32_t)__cvta_generic_to_shared(VsB + r * VST + c16),
                       vp + r * NDH + c16);
        }
        cp_commit();
    }

    for (int j = 0; j < NS / 64; j++) {
        if (j + 1 < NS / 64) {
            const int nb = (j + 1) & 1;
            const uint32_t* kp = Kg + (size_t)(j + 1) * 64 * NDH;
            const uint32_t* vp = Vg + (size_t)(j + 1) * 64 * NDH;
            uint32_t* Kn = KsB + nb * KV_TILE;
            uint32_t* Vn = VsB + nb * VV_TILE;
#pragma unroll
            for (int i = 0; i < 8; i++) {
                int r = r16 + i * 8;
                cp_async16((uint32_t)__cvta_generic_to_shared(Kn + r * KST + c16),
                           kp + r * NDH + c16);
                cp_async16((uint32_t)__cvta_generic_to_shared(Vn + r * VST + c16),
                           vp + r * NDH + c16);
            }
            cp_commit();
            cp_wait<1>();
        } else {
            cp_wait<0>();
        }
        __syncthreads();

        const uint32_t* Ks = KsB + (j & 1) * KV_TILE;
        const uint32_t* Vs = VsB + (j & 1) * VV_TILE;

        // S = Q K^T  (16x64 per warp)
        float s[8][4];
#pragma unroll
        for (int n = 0; n < 8; n++)
#pragma unroll
            for (int i = 0; i < 4; i++) s[n][i] = 0.f;
#pragma unroll
        for (int ks = 0; ks < 8; ks++) {
            const int col = ks * 8 + t;
#pragma unroll
            for (int n = 0; n < 8; n++) {
                uint32_t b[2];
                b[0] = Ks[(n * 8 + g) * KST + col];
                b[1] = Ks[(n * 8 + g) * KST + col + 4];
                mma_tf32(s[n], qf[ks], b);
            }
        }

        // online softmax (rows: row -> stats0, row+8 -> stats1)
        float mx0 = -1e30f, mx1 = -1e30f;
#pragma unroll
        for (int n = 0; n < 8; n++) {
            mx0 = fmaxf(mx0, fmaxf(s[n][0], s[n][1]));
            mx1 = fmaxf(mx1, fmaxf(s[n][2], s[n][3]));
        }
        mx0 = fmaxf(mx0, __shfl_xor_sync(0xffffffffu, mx0, 1));
        mx0 = fmaxf(mx0, __shfl_xor_sync(0xffffffffu, mx0, 2));
        mx1 = fmaxf(mx1, __shfl_xor_sync(0xffffffffu, mx1, 1));
        mx1 = fmaxf(mx1, __shfl_xor_sync(0xffffffffu, mx1, 2));
        const float mn0 = fmaxf(m0, mx0), mn1 = fmaxf(m1, mx1);
        const float sc0 = __expf(m0 - mn0), sc1 = __expf(m1 - mn1);

        float ps0 = 0.f, ps1 = 0.f;
#pragma unroll
        for (int n = 0; n < 8; n++) {
            const float p0 = __expf(s[n][0] - mn0);
            const float p1 = __expf(s[n][1] - mn0);
            const float p2 = __expf(s[n][2] - mn1);
            const float p3 = __expf(s[n][3] - mn1);
            ps0 += p0 + p1;
            ps1 += p2 + p3;
            const int c = n * 8 + 2 * t;
            *(uint2*)(Ps + row * KST + c) = make_uint2(f2tf32(p0), f2tf32(p1));
            *(uint2*)(Ps + (row + 8) * KST + c) = make_uint2(f2tf32(p2), f2tf32(p3));
            o[n][0] *= sc0; o[n][1] *= sc0;
            o[n][2] *= sc1; o[n][3] *= sc1;
        }
        ps0 += __shfl_xor_sync(0xffffffffu, ps0, 1);
        ps0 += __shfl_xor_sync(0xffffffffu, ps0, 2);
        ps1 += __shfl_xor_sync(0xffffffffu, ps1, 1);
        ps1 += __shfl_xor_sync(0xffffffffu, ps1, 2);
        l0 = l0 * sc0 + ps0;
        l1 = l1 * sc1 + ps1;
        m0 = mn0;
        m1 = mn1;
        __syncwarp();   // Ps rows are warp-private; order STS before LDS

        // O += P V   (k-dim = kv tile of 64)
#pragma unroll
        for (int ks = 0; ks < 8; ks++) {
            const int col = ks * 8 + t;
            uint32_t a[4];
            a[0] = Ps[row * KST + col];
            a[1] = Ps[(row + 8) * KST + col];
            a[2] = Ps[row * KST + col + 4];
            a[3] = Ps[(row + 8) * KST + col + 4];
#pragma unroll
            for (int n = 0; n < 8; n++) {
                uint32_t b[2];
                b[0] = Vs[(ks * 8 + t) * VST + n * 8 + g];
                b[1] = Vs[(ks * 8 + t + 4) * VST + n * 8 + g];
                mma_tf32(o[n], a, b);
            }
        }
        __syncthreads();   // all warps done with this buffer before refill
    }

    const float inv0 = 1.f / l0, inv1 = 1.f / l1;
    const int bb = bh >> 3, hh = bh & 7;
    const int r0 = qt * 64 + row;
    float* og = g_attn + ((size_t)bb * NS + r0) * ND + hh * NDH;
#pragma unroll
    for (int n = 0; n < 8; n++) {
        const int c = n * 8 + 2 * t;
        *(float2*)(og + c) = make_float2(o[n][0] * inv0, o[n][1] * inv0);
        *(float2*)(og + 8 * ND + c) = make_float2(o[n][2] * inv1, o[n][3] * inv1);
    }
}

// ---------------------------------------------------------------------------
extern "C" void kernel_launch(void* const* d_in, const int* in_sizes, int n_in,
                              void* d_out, int out_size) {
    const float* x  = (const float*)d_in[0];
    const float* Wq = (const float*)d_in[1];
    const float* Wk = (const float*)d_in[2];
    const float* Wv = (const float*)d_in[3];
    const float* Wo = (const float*)d_in[4];
    const float* bo = (const float*)d_in[5];
    float* out = (float*)d_out;

    cudaFuncSetAttribute(flash_kernel, cudaFuncAttributeMaxDynamicSharedMemorySize,
                         (int)FLASH_SMEM);

    // 1) Q,K,V = x @ {Wq,Wk,Wv}^T  -> head-split tf32-bit scratch (Q pre-scaled)
    gemm_kernel<0><<<dim3(128, 8, 3), 128>>>(x, Wq, Wk, Wv, nullptr, nullptr);
    // 2) flash attention -> g_attn [B,S,D]
    flash_kernel<<<dim3(NS / 64, NBH), 128, FLASH_SMEM>>>();
    // 3) out = g_attn @ Wo^T + bo
    gemm_kernel<1><<<dim3(128, 8, 1), 128>>>(nullptr, Wo, nullptr, nullptr, bo, out);
}

// round 6
// speedup vs baseline: 1.6799x; 1.6799x over previous
#include <cuda_runtime.h>
#include <cstdint>

#define NB 2
#define NS 4096
#define NH 8
#define NDH 64
#define ND 512
#define NBH (NB*NH)
#define NM (NB*NS)   // 8192 rows

// Scratch (allocation-free rule: __device__ globals). All tf32 BITS except g_attn epilogue note.
__device__ __align__(128) uint32_t g_xt[(size_t)NM * ND];          // x as tf32 bits
__device__ __align__(128) uint32_t g_wt[4][(size_t)ND * ND];       // Wq,Wk,Wv,Wo as tf32 bits
__device__ __align__(128) uint32_t g_Q[(size_t)NBH * NS * NDH];    // tf32 bits, pre-scaled
__device__ __align__(128) uint32_t g_K[(size_t)NBH * NS * NDH];
__device__ __align__(128) uint32_t g_V[(size_t)NBH * NS * NDH];
__device__ __align__(128) uint32_t g_attn[(size_t)NM * ND];        // tf32 bits

__device__ __forceinline__ uint32_t f2tf32(float v) {
    uint32_t u;
    asm("cvt.rna.tf32.f32 %0, %1;" : "=r"(u) : "f"(v));
    return u;
}

// D = A(16x8) * B(8x8) + D, tf32 inputs, f32 accum
__device__ __forceinline__ void mma_tf32(float* c, const uint32_t* a, const uint32_t* b) {
    asm volatile(
        "mma.sync.aligned.m16n8k8.row.col.f32.tf32.tf32.f32 "
        "{%0,%1,%2,%3}, {%4,%5,%6,%7}, {%8,%9}, {%0,%1,%2,%3};\n"
        : "+f"(c[0]), "+f"(c[1]), "+f"(c[2]), "+f"(c[3])
        : "r"(a[0]), "r"(a[1]), "r"(a[2]), "r"(a[3]), "r"(b[0]), "r"(b[1]));
}

__device__ __forceinline__ void cp_async16(uint32_t saddr, const void* gptr) {
    asm volatile("cp.async.cg.shared.global [%0], [%1], 16;\n"
                 :: "r"(saddr), "l"(gptr));
}
__device__ __forceinline__ void cp_commit() {
    asm volatile("cp.async.commit_group;\n");
}
template <int N>
__device__ __forceinline__ void cp_wait() {
    asm volatile("cp.async.wait_group %0;\n" :: "n"(N));
}
__device__ __forceinline__ uint32_t s2u(const void* p) {
    return (uint32_t)__cvta_generic_to_shared(p);
}

// ---------------------------------------------------------------------------
// One-time fp32 -> tf32-bit conversion of x and the 4 weight matrices.
// ---------------------------------------------------------------------------
__global__ __launch_bounds__(256) void cvt_x_kernel(const float* __restrict__ x) {
    const size_t i = ((size_t)blockIdx.x * 256 + threadIdx.x) * 4;
    float4 v = *(const float4*)(x + i);
    uint4 u;
    u.x = f2tf32(v.x); u.y = f2tf32(v.y); u.z = f2tf32(v.z); u.w = f2tf32(v.w);
    *(uint4*)(g_xt + i) = u;
}

__global__ __launch_bounds__(256) void cvt_w_kernel(
    const float* __restrict__ Wq, const float* __restrict__ Wk,
    const float* __restrict__ Wv, const float* __restrict__ Wo) {
    const float* s = (blockIdx.y == 0) ? Wq : (blockIdx.y == 1) ? Wk
                     : (blockIdx.y == 2) ? Wv : Wo;
    const size_t i = ((size_t)blockIdx.x * 256 + threadIdx.x) * 4;
    float4 v = *(const float4*)(s + i);
    uint4 u;
    u.x = f2tf32(v.x); u.y = f2tf32(v.y); u.z = f2tf32(v.z); u.w = f2tf32(v.w);
    *(uint4*)(g_wt[blockIdx.y] + i) = u;
}

// ---------------------------------------------------------------------------
// GEMM: out[m,n] = sum_k A[m,k] * W[n,k]  (inputs are tf32 bits in global)
// CTA tile 64x64, 4 warps, BK=32, 2-stage cp.async double buffering,
// batched fragment loads (16 B-frag LDS issued before the 8 MMAs consume).
// MODE 0: A = g_xt, W = g_wt[z]; writes head-split tf32 bits to g_Q/g_K/g_V
//         (Q scaled by 0.125 = Dh^-0.5, exact pow2).
// MODE 1: A = g_attn, W = g_wt[3]; writes fp32 + bias into out.
// ---------------------------------------------------------------------------
template <int MODE>
__global__ __launch_bounds__(128) void gemm_kernel(
    const float* __restrict__ bias, float* __restrict__ out)
{
    __shared__ uint32_t As[2][64][36];   // stride 36: conflict-free fragments
    __shared__ uint32_t Bs[2][64][36];

    const int tid = threadIdx.x;
    const int warp = tid >> 5, lane = tid & 31, g = lane >> 2, t = lane & 3;
    const int m0 = blockIdx.x * 64, n0 = blockIdx.y * 64;

    const uint32_t* Ap = (MODE == 0) ? g_xt : g_attn;
    const uint32_t* W = (MODE == 0) ? g_wt[blockIdx.z] : g_wt[3];

    const int fr = tid >> 3, fc = (tid & 7) << 2;   // fill: 16 rows/iter x 8 chunks

    float acc[8][4];
#pragma unroll
    for (int n = 0; n < 8; n++)
#pragma unroll
        for (int i = 0; i < 4; i++) acc[n][i] = 0.f;

    // prologue fill stage 0
#pragma unroll
    for (int i = 0; i < 4; i++) {
        int r = fr + i * 16;
        cp_async16(s2u(&As[0][r][fc]), Ap + (size_t)(m0 + r) * ND + fc);
        cp_async16(s2u(&Bs[0][r][fc]), W + (size_t)(n0 + r) * ND + fc);
    }
    cp_commit();

    for (int kt = 0; kt < 16; kt++) {
        cp_wait<0>();
        __syncthreads();
        if (kt < 15) {
            const int st = (kt + 1) & 1, ko = (kt + 1) * 32;
#pragma unroll
            for (int i = 0; i < 4; i++) {
                int r = fr + i * 16;
                cp_async16(s2u(&As[st][r][fc]), Ap + (size_t)(m0 + r) * ND + ko + fc);
                cp_async16(s2u(&Bs[st][r][fc]), W + (size_t)(n0 + r) * ND + ko + fc);
            }
            cp_commit();
        }
        const uint32_t (*A_)[36] = As[kt & 1];
        const uint32_t (*B_)[36] = Bs[kt & 1];
        const int row = warp * 16 + g;

        uint32_t af[4];
        af[0] = A_[row][t];
        af[1] = A_[row + 8][t];
        af[2] = A_[row][t + 4];
        af[3] = A_[row + 8][t + 4];
#pragma unroll
        for (int ks = 0; ks < 4; ks++) {
            uint32_t bf[8][2];
            const int col = ks * 8 + t;
#pragma unroll
            for (int n = 0; n < 8; n++) {
                bf[n][0] = B_[n * 8 + g][col];
                bf[n][1] = B_[n * 8 + g][col + 4];
            }
            uint32_t an[4];
            if (ks < 3) {
                const int c2 = col + 8;
                an[0] = A_[row][c2];
                an[1] = A_[row + 8][c2];
                an[2] = A_[row][c2 + 4];
                an[3] = A_[row + 8][c2 + 4];
            }
#pragma unroll
            for (int n = 0; n < 8; n++) mma_tf32(acc[n], af, bf[n]);
            if (ks < 3) {
                af[0] = an[0]; af[1] = an[1]; af[2] = an[2]; af[3] = an[3];
            }
        }
        // no trailing sync needed: top-of-loop wait+sync protects stage reuse
    }

    const int r = m0 + warp * 16 + g;
    if (MODE == 0) {
        uint32_t* dst = blockIdx.z == 0 ? g_Q : (blockIdx.z == 1 ? g_K : g_V);
        const float scl = (blockIdx.z == 0) ? 0.125f : 1.0f;
        const int bb = r >> 12, ss = r & (NS - 1);
#pragma unroll
        for (int n = 0; n < 8; n++) {
            const int c = n0 + n * 8 + 2 * t;
            const int hh = c >> 6, dd = c & 63;
            const size_t base = (((size_t)(bb * NH + hh)) * NS + ss) * NDH + dd;
            dst[base] = f2tf32(acc[n][0] * scl);
            dst[base + 1] = f2tf32(acc[n][1] * scl);
            dst[base + 8 * NDH] = f2tf32(acc[n][2] * scl);
            dst[base + 8 * NDH + 1] = f2tf32(acc[n][3] * scl);
        }
    } else {
#pragma unroll
        for (int n = 0; n < 8; n++) {
            const int c = n0 + n * 8 + 2 * t;
            const float b0v = bias[c], b1v = bias[c + 1];
            out[(size_t)r * ND + c] = acc[n][0] + b0v;
            out[(size_t)r * ND + c + 1] = acc[n][1] + b1v;
            out[(size_t)(r + 8) * ND + c] = acc[n][2] + b0v;
            out[(size_t)(r + 8) * ND + c + 1] = acc[n][3] + b1v;
        }
    }
}

// ---------------------------------------------------------------------------
// Flash attention: grid (S/64, B*H), 128 threads (4 warps, 16 Q-rows each).
// Q fragments resident in registers (tf32 bits). K double-buffered via
// cp.async (prefetched during previous tile's compute); V single-buffered,
// issued right after PV so the next QK covers its latency. P staged in smem
// as tf32 bits. smem = 62.7 KB -> 3 CTAs/SM.
// ---------------------------------------------------------------------------
#define KST 68   // K/P stride: (4g+t) fragment patterns conflict-free
#define VST 72   // V stride: (8t+g) fragment patterns conflict-free
#define KV_TILE (64 * KST)
#define VV_TILE (64 * VST)
#define FLASH_SMEM ((2 * KV_TILE + VV_TILE + 64 * KST) * sizeof(uint32_t))

__global__ __launch_bounds__(128, 3) void flash_kernel() {
    extern __shared__ uint32_t sm[];
    uint32_t* KsB = sm;                     // 2 stages
    uint32_t* Vs = sm + 2 * KV_TILE;        // 1 stage
    uint32_t* Ps = Vs + VV_TILE;

    const int tid = threadIdx.x;
    const int warp = tid >> 5, lane = tid & 31, g = lane >> 2, t = lane & 3;
    const int bh = blockIdx.y, qt = blockIdx.x;
    const int row = warp * 16 + g;

    const uint32_t* Qg = g_Q + (size_t)(bh * NS + qt * 64) * NDH;
    const uint32_t* Kg = g_K + (size_t)bh * NS * NDH;
    const uint32_t* Vg = g_V + (size_t)bh * NS * NDH;

    // Preload Q fragments (resident whole kernel): 32 regs of tf32 bits
    uint32_t qf[8][4];
#pragma unroll
    for (int ks = 0; ks < 8; ks++) {
        const int col = ks * 8 + t;
        qf[ks][0] = Qg[row * NDH + col];
        qf[ks][1] = Qg[(row + 8) * NDH + col];
        qf[ks][2] = Qg[row * NDH + col + 4];
        qf[ks][3] = Qg[(row + 8) * NDH + col + 4];
    }

    float o[8][4];
#pragma unroll
    for (int n = 0; n < 8; n++)
#pragma unroll
        for (int i = 0; i < 4; i++) o[n][i] = 0.f;
    float m0 = -1e30f, m1 = -1e30f, l0 = 0.f, l1 = 0.f;

    const int r16 = tid >> 4, c16 = (tid & 15) << 2;

    // prologue: K(0) then V(0) (commit order matters for wait accounting)
#pragma unroll
    for (int i = 0; i < 8; i++) {
        int r = r16 + i * 8;
        cp_async16(s2u(KsB + r * KST + c16), Kg + r * NDH + c16);
    }
    cp_commit();
#pragma unroll
    for (int i = 0; i < 8; i++) {
        int r = r16 + i * 8;
        cp_async16(s2u(Vs + r * VST + c16), Vg + r * NDH + c16);
    }
    cp_commit();

    for (int j = 0; j < NS / 64; j++) {
        // pending groups here: K(j), V(j)  ->  wait<1> retires K(j)
        cp_wait<1>();
        __syncthreads();
        if (j + 1 < NS / 64) {   // prefetch K(j+1) into the other stage
            const uint32_t* kp = Kg + (size_t)(j + 1) * 64 * NDH;
            uint32_t* Kn = KsB + ((j + 1) & 1) * KV_TILE;
#pragma unroll
            for (int i = 0; i < 8; i++) {
                int r = r16 + i * 8;
                cp_async16(s2u(Kn + r * KST + c16), kp + r * NDH + c16);
            }
            cp_commit();
        }
        const uint32_t* Ks = KsB + (j & 1) * KV_TILE;

        // S = Q K^T  (16x64 per warp), batched B-fragment loads per k-step
        float s[8][4];
#pragma unroll
        for (int n = 0; n < 8; n++)
#pragma unroll
            for (int i = 0; i < 4; i++) s[n][i] = 0.f;
#pragma unroll
        for (int ks = 0; ks < 8; ks++) {
            const int col = ks * 8 + t;
            uint32_t bf[8][2];
#pragma unroll
            for (int n = 0; n < 8; n++) {
                bf[n][0] = Ks[(n * 8 + g) * KST + col];
                bf[n][1] = Ks[(n * 8 + g) * KST + col + 4];
            }
#pragma unroll
            for (int n = 0; n < 8; n++) mma_tf32(s[n], qf[ks], bf[n]);
        }

        // online softmax (rows: row -> stats0, row+8 -> stats1)
        float mx0 = -1e30f, mx1 = -1e30f;
#pragma unroll
        for (int n = 0; n < 8; n++) {
            mx0 = fmaxf(mx0, fmaxf(s[n][0], s[n][1]));
            mx1 = fmaxf(mx1, fmaxf(s[n][2], s[n][3]));
        }
        mx0 = fmaxf(mx0, __shfl_xor_sync(0xffffffffu, mx0, 1));
        mx0 = fmaxf(mx0, __shfl_xor_sync(0xffffffffu, mx0, 2));
        mx1 = fmaxf(mx1, __shfl_xor_sync(0xffffffffu, mx1, 1));
        mx1 = fmaxf(mx1, __shfl_xor_sync(0xffffffffu, mx1, 2));
        const float mn0 = fmaxf(m0, mx0), mn1 = fmaxf(m1, mx1);
        const float sc0 = __expf(m0 - mn0), sc1 = __expf(m1 - mn1);

        float ps0 = 0.f, ps1 = 0.f;
#pragma unroll
        for (int n = 0; n < 8; n++) {
            const float p0 = __expf(s[n][0] - mn0);
            const float p1 = __expf(s[n][1] - mn0);
            const float p2 = __expf(s[n][2] - mn1);
            const float p3 = __expf(s[n][3] - mn1);
            ps0 += p0 + p1;
            ps1 += p2 + p3;
            const int c = n * 8 + 2 * t;
            *(uint2*)(Ps + row * KST + c) = make_uint2(f2tf32(p0), f2tf32(p1));
            *(uint2*)(Ps + (row + 8) * KST + c) = make_uint2(f2tf32(p2), f2tf32(p3));
            o[n][0] *= sc0; o[n][1] *= sc0;
            o[n][2] *= sc1; o[n][3] *= sc1;
        }
        ps0 += __shfl_xor_sync(0xffffffffu, ps0, 1);
        ps0 += __shfl_xor_sync(0xffffffffu, ps0, 2);
        ps1 += __shfl_xor_sync(0xffffffffu, ps1, 1);
        ps1 += __shfl_xor_sync(0xffffffffu, ps1, 2);
        l0 = l0 * sc0 + ps0;
        l1 = l1 * sc1 + ps1;
        m0 = mn0;
        m1 = mn1;

        // pending: V(j) [+ K(j+1) if issued]  ->  retire V(j)
        if (j + 1 < NS / 64) cp_wait<1>(); else cp_wait<0>();
        __syncthreads();   // V visible to all; also orders Ps stores

        // O += P V   (k-dim = kv tile of 64)
#pragma unroll
        for (int ks = 0; ks < 8; ks++) {
            const int col = ks * 8 + t;
            uint32_t a[4];
            a[0] = Ps[row * KST + col];
            a[1] = Ps[(row + 8) * KST + col];
            a[2] = Ps[row * KST + col + 4];
            a[3] = Ps[(row + 8) * KST + col + 4];
            uint32_t bf[8][2];
#pragma unroll
            for (int n = 0; n < 8; n++) {
                bf[n][0] = Vs[(ks * 8 + t) * VST + n * 8 + g];
                bf[n][1] = Vs[(ks * 8 + t + 4) * VST + n * 8 + g];
            }
#pragma unroll
            for (int n = 0; n < 8; n++) mma_tf32(o[n], a, bf[n]);
        }
        __syncthreads();   // all readers of Vs/Ps done before refilling V

        if (j + 1 < NS / 64) {   // V(j+1): latency covered by next QK
            const uint32_t* vp = Vg + (size_t)(j + 1) * 64 * NDH;
#pragma unroll
            for (int i = 0; i < 8; i++) {
                int r = r16 + i * 8;
                cp_async16(s2u(Vs + r * VST + c16), vp + r * NDH + c16);
            }
            cp_commit();
        }
    }

    const float inv0 = 1.f / l0, inv1 = 1.f / l1;
    const int bb = bh >> 3, hh = bh & 7;
    const int r0 = qt * 64 + row;
    uint32_t* og = g_attn + ((size_t)bb * NS + r0) * ND + hh * NDH;
#pragma unroll
    for (int n = 0; n < 8; n++) {
        const int c = n * 8 + 2 * t;
        *(uint2*)(og + c) =
            make_uint2(f2tf32(o[n][0] * inv0), f2tf32(o[n][1] * inv0));
        *(uint2*)(og + 8 * ND + c) =
            make_uint2(f2tf32(o[n][2] * inv1), f2tf32(o[n][3] * inv1));
    }
}

// ---------------------------------------------------------------------------
extern "C" void kernel_launch(void* const* d_in, const int* in_sizes, int n_in,
                              void* d_out, int out_size) {
    const float* x  = (const float*)d_in[0];
    const float* Wq = (const float*)d_in[1];
    const float* Wk = (const float*)d_in[2];
    const float* Wv = (const float*)d_in[3];
    const float* Wo = (const float*)d_in[4];
    const float* bo = (const float*)d_in[5];
    float* out = (float*)d_out;

    cudaFuncSetAttribute(flash_kernel, cudaFuncAttributeMaxDynamicSharedMemorySize,
                         (int)FLASH_SMEM);

    // 0) one-shot fp32 -> tf32-bit conversion of x and weights
    cvt_x_kernel<<<(NM * ND) / (256 * 4), 256>>>(x);
    cvt_w_kernel<<<dim3((ND * ND) / (256 * 4), 4), 256>>>(Wq, Wk, Wv, Wo);
    // 1) Q,K,V = x @ {Wq,Wk,Wv}^T  -> head-split tf32-bit scratch (Q pre-scaled)
    gemm_kernel<0><<<dim3(NM / 64, ND / 64, 3), 128>>>(nullptr, nullptr);
    // 2) flash attention -> g_attn (tf32 bits, [B,S,D])
    flash_kernel<<<dim3(NS / 64, NBH), 128, FLASH_SMEM>>>();
    // 3) out = attn @ Wo^T + bo  (fp32 out)
    gemm_kernel<1><<<dim3(NM / 64, ND / 64, 1), 128>>>(bo, out);
}